// round 5
// baseline (speedup 1.0000x reference)
#include <cuda_runtime.h>
#include <math.h>

#define BB 16
#define DD 512
#define HH 16
#define HD 32
#define LL 24
#define DFF 2048
#define NQKV 1536
#define TMAX 1024
#define NT 512
#define NCH 2  // attention T-chunks

// ---------------- device scratch ----------------
__device__ float g_h[BB * DD];            // layer input (post LN2 of prev layer)
__device__ float g_h1[BB * DD];           // post-LN1 hidden
__device__ float g_pqkv[8 * BB * NQKV];   // qkv K-partials
__device__ float g_po[16 * BB * DD];      // outproj K-partials
__device__ float g_pm1[4 * BB * DFF];     // mlp1 K-partials
__device__ float g_p2[16 * BB * DD];      // mlp2 K-partials
__device__ float g_am[BB * HH * NCH];     // per-chunk softmax max
__device__ float g_as[BB * HH * NCH];     // per-chunk exp-sum
__device__ float g_ao[NCH * BB * HH * HD];// per-chunk unnormalized V-acc
__device__ unsigned g_bar_count;
__device__ volatile unsigned g_bar_gen;

// ---------------- grid barrier ----------------
__device__ __forceinline__ void gsync() {
    __syncthreads();
    if (threadIdx.x == 0) {
        unsigned gen = g_bar_gen;
        __threadfence();
        if (atomicAdd(&g_bar_count, 1u) == gridDim.x - 1) {
            g_bar_count = 0;
            __threadfence();
            g_bar_gen = gen + 1;
        } else {
            while (g_bar_gen == gen) __nanosleep(64);
            __threadfence();
        }
    }
    __syncthreads();
}

// ---------------- L2 prefetch: stripe `lines` 128B lines over the grid ---
__device__ __forceinline__ void prefetch_l2(const float* __restrict__ base,
                                            int lines) {
    for (int i = blockIdx.x * NT + threadIdx.x; i < lines;
         i += gridDim.x * NT)
        asm volatile("prefetch.global.L2 [%0];" :: "l"(base + (size_t)i * 32));
}

// ---------------- preloads: fill xs[d][b] (stride 20) for all 16 batches -
template <int DS>
__device__ __forceinline__ void preload_plain(const float* __restrict__ src,
                                              int ld, int d0, float* xs) {
    const int tid = threadIdx.x;
#pragma unroll
    for (int i = tid; i < DS * BB; i += NT) {
        int bb = i / DS, d = i % DS;
        xs[d * 20 + bb] = src[(size_t)bb * ld + d0 + d];
    }
    __syncthreads();
}

// mlp2 preload: relu(b1 + sum of 4 mlp1 partials), DS=128
__device__ __forceinline__ void preload_relu(const float* __restrict__ b1,
                                             int d0, float* xs) {
    const int tid = threadIdx.x;
#pragma unroll
    for (int i = tid; i < 128 * BB; i += NT) {
        int bb = i >> 7, d = i & 127;
        int gd = d0 + d;
        float v = b1[gd];
#pragma unroll
        for (int s = 0; s < 4; s++)
            v += g_pm1[(size_t)(s * BB + bb) * DFF + gd];
        xs[d * 20 + bb] = fmaxf(v, 0.f);
    }
    __syncthreads();
}

// outproj preload: merge NCH attention chunks for head h (DS=32)
__device__ __forceinline__ void preload_attn(int h, float* xs) {
    const int tid = threadIdx.x;
    const int bb = tid >> 5, j = tid & 31;  // 16 batches x 32 dims = 512
    const int base = (bb * HH + h) * NCH;
    float m0 = g_am[base + 0], m1 = g_am[base + 1];
    float m = fmaxf(m0, m1);
    float w0 = __expf(m0 - m), w1 = __expf(m1 - m);
    float S = g_as[base + 0] * w0 + g_as[base + 1] * w1;
    const size_t ob = ((size_t)bb * HH + h) * HD + j;
    float o = g_ao[ob] * w0 + g_ao[(size_t)BB * HH * HD + ob] * w1;
    xs[j * 20 + bb] = o / S;
    __syncthreads();
}

// ---------------- gemv core: 32 cols x 16 batches over DS K-dims ---------
// 16 warps each handle DS/16 K-dims; smem cross-warp reduction.
template <int DS>
__device__ __forceinline__ void gemv_core(const float* __restrict__ W, int N,
                                          int d0, int c0,
                                          float* __restrict__ out, int ldo,
                                          float* xs, float* red) {
    const int tid = threadIdx.x, lane = tid & 31, w = tid >> 5;
    constexpr int DW = DS / 16;
    const float* Wp = W + (size_t)(d0 + w * DW) * N + c0 + lane;
    const float* xp = xs + (size_t)(w * DW) * 20;
    float acc[16];
#pragma unroll
    for (int b = 0; b < 16; b++) acc[b] = 0.f;
#pragma unroll
    for (int d = 0; d < DW; d++) {
        float wv = Wp[(size_t)d * N];
        float4 x0 = *(const float4*)(xp + d * 20);
        float4 x1 = *(const float4*)(xp + d * 20 + 4);
        float4 x2 = *(const float4*)(xp + d * 20 + 8);
        float4 x3 = *(const float4*)(xp + d * 20 + 12);
        acc[0]  += x0.x * wv; acc[1]  += x0.y * wv;
        acc[2]  += x0.z * wv; acc[3]  += x0.w * wv;
        acc[4]  += x1.x * wv; acc[5]  += x1.y * wv;
        acc[6]  += x1.z * wv; acc[7]  += x1.w * wv;
        acc[8]  += x2.x * wv; acc[9]  += x2.y * wv;
        acc[10] += x2.z * wv; acc[11] += x2.w * wv;
        acc[12] += x3.x * wv; acc[13] += x3.y * wv;
        acc[14] += x3.z * wv; acc[15] += x3.w * wv;
    }
    float* rp = red + (size_t)tid * 17;
#pragma unroll
    for (int b = 0; b < 16; b++) rp[b] = acc[b];
    __syncthreads();
    const int cc = tid & 31, bb = tid >> 5;  // 32 cols x 16 batches
    float v = 0.f;
#pragma unroll
    for (int w2 = 0; w2 < 16; w2++) v += red[(size_t)(w2 * 32 + cc) * 17 + bb];
    out[(size_t)bb * ldo + c0 + cc] = v;
    __syncthreads();
}

// ---------------- attention chunk: one (b, h, c), 512 threads ------------
__device__ void attn_chunk(const float* __restrict__ Kc, const float* __restrict__ Vc,
                           const float* __restrict__ bq,
                           const int* __restrict__ kvlen,
                           int b, int h, int c, float* sm) {
    float* sc   = sm;          // [520]
    float* qs   = sm + 520;    // [32]
    float* kns  = sm + 552;    // [32]
    float* vns  = sm + 584;    // [32]
    float* redv = sm + 616;    // [16][32]
    float* rr   = sm + 1128;   // [16]
    float* fin  = sm + 1144;   // [2]

    const int tid = threadIdx.x, wid = tid >> 5, lane = tid & 31;
    const int T = kvlen[b];
    const int Ttot = T + 1;
    const int CH = (Ttot + NCH - 1) / NCH;
    const int t0 = c * CH;
    const int t1 = (t0 + CH < Ttot) ? (t0 + CH) : Ttot;
    const float scale = 0.17677669529663687f;

    // merge qkv partials for q / k_new / v_new
    if (tid < 96) {
        int which = tid >> 5, j = tid & 31;
        int col = which * DD + h * HD + j;
        float v = bq[col];
#pragma unroll
        for (int s = 0; s < 8; s++) v += g_pqkv[(size_t)(s * BB + b) * NQKV + col];
        if (which == 0) qs[j] = v;
        else if (which == 1) kns[j] = v;
        else vns[j] = v;
    }
    __syncthreads();

    const int outi = (b * HH + h) * NCH + c;
    const size_t ob = ((size_t)b * HH + h) * HD;

    if (t1 <= t0) {
        if (tid == 0) { g_am[outi] = -1e30f; g_as[outi] = 0.f; }
        if (tid < HD) g_ao[(size_t)(c * BB) * HH * HD + ob + tid] = 0.f;
        return;
    }

    const float* Kb = Kc + ((size_t)b * HH + h) * TMAX * HD;
    const float* Vb = Vc + ((size_t)b * HH + h) * TMAX * HD;
    const int len = t1 - t0;

    // score pass: thread per timestep
    for (int t = t0 + tid; t < t1; t += NT) {
        const float* kp = (t < T) ? (Kb + (size_t)t * HD) : kns;
        float s = 0.f;
#pragma unroll
        for (int i = 0; i < 8; i++) {
            float4 k4 = *(const float4*)(kp + i * 4);
            float4 q4 = *(const float4*)(qs + i * 4);
            s += k4.x * q4.x + k4.y * q4.y + k4.z * q4.z + k4.w * q4.w;
        }
        sc[t - t0] = s * scale;
    }
    __syncthreads();

    // chunk max
    float m = -1e30f;
    for (int i = tid; i < len; i += NT) m = fmaxf(m, sc[i]);
#pragma unroll
    for (int o = 16; o; o >>= 1) m = fmaxf(m, __shfl_xor_sync(0xffffffffu, m, o));
    if (lane == 0) rr[wid] = m;
    __syncthreads();
    if (tid == 0) {
        float mm = rr[0];
#pragma unroll
        for (int w = 1; w < 16; w++) mm = fmaxf(mm, rr[w]);
        fin[0] = mm;
    }
    __syncthreads();
    m = fin[0];

    // exp + sum
    float s = 0.f;
    for (int i = tid; i < len; i += NT) {
        float e = __expf(sc[i] - m);
        sc[i] = e;
        s += e;
    }
#pragma unroll
    for (int o = 16; o; o >>= 1) s += __shfl_xor_sync(0xffffffffu, s, o);
    if (lane == 0) rr[wid] = s;
    __syncthreads();
    if (tid == 0) {
        float ss = rr[0];
#pragma unroll
        for (int w = 1; w < 16; w++) ss += rr[w];
        g_am[outi] = m;
        g_as[outi] = ss;
    }

    // V pass: warp covers 4 timesteps/iter (unnormalized accumulation)
    const int tq = lane >> 3, dq = lane & 7;
    float4 acc = make_float4(0.f, 0.f, 0.f, 0.f);
#pragma unroll 2
    for (int t = t0 + wid * 4 + tq; t < t1; t += 64) {
        float wgt = sc[t - t0];
        const float* vp = (t < T) ? (Vb + (size_t)t * HD) : vns;
        float4 v4 = *(const float4*)(vp + dq * 4);
        acc.x += wgt * v4.x; acc.y += wgt * v4.y;
        acc.z += wgt * v4.z; acc.w += wgt * v4.w;
    }
#pragma unroll
    for (int o = 8; o <= 16; o <<= 1) {
        acc.x += __shfl_xor_sync(0xffffffffu, acc.x, o);
        acc.y += __shfl_xor_sync(0xffffffffu, acc.y, o);
        acc.z += __shfl_xor_sync(0xffffffffu, acc.z, o);
        acc.w += __shfl_xor_sync(0xffffffffu, acc.w, o);
    }
    if (tq == 0) *(float4*)(redv + wid * 32 + dq * 4) = acc;
    __syncthreads();
    if (tid < HD) {
        float o = 0.f;
#pragma unroll
        for (int w = 0; w < 16; w++) o += redv[w * 32 + tid];
        g_ao[(size_t)(c * BB) * HH * HD + ob + tid] = o;
    }
}

// ---------------- LN stage: one batch (512 threads, 1 dim each) ----------
template <int S>
__device__ void ln_stage(const float* __restrict__ part,
                         const float* __restrict__ resid,
                         const float* __restrict__ bias,
                         const float* __restrict__ gam,
                         const float* __restrict__ bet,
                         float* __restrict__ out, int b, float* sm) {
    const int tid = threadIdx.x, lane = tid & 31, wid = tid >> 5;
    float v = resid[(size_t)b * DD + tid] + bias[tid];
#pragma unroll
    for (int s = 0; s < S; s++) v += part[(size_t)(s * BB + b) * DD + tid];
    float s1 = v, s2 = v * v;
#pragma unroll
    for (int o = 16; o; o >>= 1) {
        s1 += __shfl_xor_sync(0xffffffffu, s1, o);
        s2 += __shfl_xor_sync(0xffffffffu, s2, o);
    }
    float* rs = sm; float* rq = sm + 16; float* mv = sm + 32;
    if (lane == 0) { rs[wid] = s1; rq[wid] = s2; }
    __syncthreads();
    if (tid == 0) {
        float a = 0.f, q = 0.f;
#pragma unroll
        for (int w = 0; w < 16; w++) { a += rs[w]; q += rq[w]; }
        float mean = a / DD;
        mv[0] = mean;
        mv[1] = rsqrtf(q / DD - mean * mean + 1e-5f);
    }
    __syncthreads();
    out[(size_t)b * DD + tid] = (v - mv[0]) * mv[1] * gam[tid] + bet[tid];
    __syncthreads();
}

// ---------------- persistent kernel ----------------
__global__ void __launch_bounds__(NT, 2)
decoder_kernel(const float* __restrict__ x,
               const float* __restrict__ kc, const float* __restrict__ vc,
               const float* __restrict__ ln1g, const float* __restrict__ ln1b,
               const float* __restrict__ qkvw, const float* __restrict__ qkvb,
               const float* __restrict__ outw, const float* __restrict__ outb,
               const float* __restrict__ ln2g, const float* __restrict__ ln2b,
               const float* __restrict__ w1, const float* __restrict__ b1,
               const float* __restrict__ w2, const float* __restrict__ b2,
               const int* __restrict__ kvlen, float* __restrict__ dout) {
    extern __shared__ float sm[];
    float* xs  = sm;             // [128][20] max
    float* red = sm + 128 * 20;  // [512][17]

    for (int l = 0; l < LL; l++) {
        const float* Wq = qkvw + (size_t)l * DD * NQKV;
        const float* bq = qkvb + (size_t)l * NQKV;
        const float* Wo = outw + (size_t)l * DD * DD;
        const float* bo = outb + (size_t)l * DD;
        const float* W1 = w1 + (size_t)l * DD * DFF;
        const float* B1 = b1 + (size_t)l * DFF;
        const float* W2 = w2 + (size_t)l * DFF * DD;
        const float* Kc = kc + (size_t)l * BB * HH * TMAX * HD;
        const float* Vc = vc + (size_t)l * BB * HH * TMAX * HD;

        // S0: g_h (x copy for l==0, else LN2) + prefetch Wq into L2.
        prefetch_l2(Wq, DD * NQKV / 32);
        if (l == 0) {
            for (int i = blockIdx.x * NT + threadIdx.x; i < BB * DD;
                 i += gridDim.x * NT)
                g_h[i] = x[i];
        } else {
            for (int vb = blockIdx.x; vb < 16; vb += gridDim.x)
                ln_stage<16>(g_p2, g_h1, b2 + (size_t)(l - 1) * DD,
                             ln2g + (size_t)(l - 1) * DD,
                             ln2b + (size_t)(l - 1) * DD, g_h, vb, sm);
        }
        gsync();

        // S1: qkv split-K8 (DS=64). 384 vblocks.
        for (int vb = blockIdx.x; vb < 384; vb += gridDim.x) {
            int ks = vb & 7, c0 = (vb >> 3) * 32;
            preload_plain<64>(g_h, DD, ks * 64, xs);
            gemv_core<64>(Wq, NQKV, ks * 64, c0,
                          g_pqkv + (size_t)ks * BB * NQKV, NQKV, xs, red);
        }
        gsync();

        // S2: attention T-split 2 (512 vblocks) + prefetch Wo/W1/W2.
        prefetch_l2(Wo, DD * DD / 32);
        prefetch_l2(W1, DD * DFF / 32);
        prefetch_l2(W2, DFF * DD / 32);
        for (int vb = blockIdx.x; vb < 512; vb += gridDim.x) {
            int c = vb & 1, h = (vb >> 1) & 15, b = vb >> 5;
            attn_chunk(Kc, Vc, bq, kvlen, b, h, c, sm);
        }
        gsync();

        // S3: outproj split-K16 (DS=32), attn merge in preload. 256 vblocks.
        for (int vb = blockIdx.x; vb < 256; vb += gridDim.x) {
            int ks = vb & 15, c0 = (vb >> 4) * 32;
            preload_attn(ks, xs);  // h == ks (DS == HD)
            gemv_core<32>(Wo, DD, ks * 32, c0,
                          g_po + (size_t)ks * BB * DD, DD, xs, red);
        }
        gsync();

        // S4: LN1 (merge 16 partials + residual g_h + bo). 16 vblocks.
        for (int vb = blockIdx.x; vb < 16; vb += gridDim.x)
            ln_stage<16>(g_po, g_h, bo, ln1g + (size_t)l * DD,
                         ln1b + (size_t)l * DD, g_h1, vb, sm);
        gsync();

        // S5: mlp1 split-K4 (DS=128). 256 vblocks.
        for (int vb = blockIdx.x; vb < 256; vb += gridDim.x) {
            int ks = vb & 3, c0 = (vb >> 2) * 32;
            preload_plain<128>(g_h1, DD, ks * 128, xs);
            gemv_core<128>(W1, DFF, ks * 128, c0,
                           g_pm1 + (size_t)ks * BB * DFF, DFF, xs, red);
        }
        gsync();

        // S6: mlp2 split-K16 (DS=128), relu+merge in preload. 256 vblocks.
        for (int vb = blockIdx.x; vb < 256; vb += gridDim.x) {
            int ks = vb & 15, c0 = (vb >> 4) * 32;
            preload_relu(B1, ks * 128, xs);
            gemv_core<128>(W2, DD, ks * 128, c0,
                           g_p2 + (size_t)ks * BB * DD, DD, xs, red);
        }
        gsync();
    }

    // final: LN2 of last layer -> d_out. 16 vblocks.
    for (int vb = blockIdx.x; vb < 16; vb += gridDim.x)
        ln_stage<16>(g_p2, g_h1, b2 + (size_t)(LL - 1) * DD,
                     ln2g + (size_t)(LL - 1) * DD,
                     ln2b + (size_t)(LL - 1) * DD, dout, vb, sm);
}

// ---------------- launcher ----------------
extern "C" void kernel_launch(void* const* d_in, const int* in_sizes, int n_in,
                              void* d_out, int out_size) {
    (void)in_sizes; (void)n_in; (void)out_size;
    const float* x    = (const float*)d_in[0];
    const float* kc   = (const float*)d_in[1];
    const float* vc   = (const float*)d_in[2];
    const float* ln1g = (const float*)d_in[3];
    const float* ln1b = (const float*)d_in[4];
    const float* qkvw = (const float*)d_in[5];
    const float* qkvb = (const float*)d_in[6];
    const float* outw = (const float*)d_in[7];
    const float* outb = (const float*)d_in[8];
    const float* ln2g = (const float*)d_in[9];
    const float* ln2b = (const float*)d_in[10];
    const float* w1   = (const float*)d_in[11];
    const float* b1   = (const float*)d_in[12];
    const float* w2   = (const float*)d_in[13];
    const float* b2   = (const float*)d_in[14];
    const int* kvlen  = (const int*)d_in[16];

    static int grid = 0;
    const int SMEM = (128 * 20 + 512 * 17) * 4;  // 45056 bytes
    if (!grid) {
        cudaFuncSetAttribute(decoder_kernel,
                             cudaFuncAttributeMaxDynamicSharedMemorySize, SMEM);
        int dev = 0;
        cudaGetDevice(&dev);
        cudaDeviceProp prop;
        cudaGetDeviceProperties(&prop, dev);
        int occ = 0;
        cudaOccupancyMaxActiveBlocksPerMultiprocessor(&occ, decoder_kernel,
                                                      NT, SMEM);
        if (occ < 1) occ = 1;
        if (occ > 2) occ = 2;
        grid = prop.multiProcessorCount * occ;
    }

    decoder_kernel<<<grid, NT, SMEM>>>(
        x, kc, vc, ln1g, ln1b, qkvw, qkvb, outw, outb, ln2g, ln2b,
        w1, b1, w2, b2, kvlen, (float*)d_out);
}